// round 15
// baseline (speedup 1.0000x reference)
#include <cuda_runtime.h>
#include <math.h>

#define BB      16
#define NA      286
#define NAP     288       // padded atom count (multiple of 8)
#define HID     150
#define FF      512
#define RADIUS_F 3.0f
#define MT      128       // table knots per cloud
#define PTS     4         // points per build block
#define CH      10        // k-chunk (prefetch depth) in build
#define NBLK    (NAP/8)   // conv tiles per batch (36)
#define NBLOCKS (NBLK*BB) // 576 persistent blocks

// ---------------- scratch (device globals; no allocation allowed) ----------
__device__ __align__(16) float g_feats0[BB*NA*4];
__device__ __align__(16) float g_f1[BB*NA*4];
// paired-knot table: row i holds {K_i[q][0..3], K_{i+1}[q][0..3]} for q=0..3
__device__ __align__(16) float g_tab2[2][MT*32];
__device__ float g_nbinv[BB*NA];
// per-pair replay: {tt, offset-as-int-bits}; offset<0 => miss
__device__ __align__(16) float2 g_uv[(size_t)BB*NAP*NAP];
__device__ float g_part[BB][NBLK][8];    // per-block pooled partial sums
__device__ float g_hpart[8][BB];         // per-head-block output partials

// grid-barrier state (generation counter survives across launches)
__device__ int          g_cnt;
__device__ volatile int g_gen;

__device__ __forceinline__ void grid_sync() {
    __threadfence();
    __syncthreads();
    if (threadIdx.x == 0) {
        int gen = g_gen;
        if (atomicAdd(&g_cnt, 1) == NBLOCKS - 1) {
            g_cnt = 0;
            __threadfence();
            g_gen = gen + 1;
        } else {
            while (g_gen == gen) __nanosleep(64);
        }
    }
    __syncthreads();
}

__device__ __forceinline__ float sp5(float x) {
    float z = 5.0f * x;
    return (fmaxf(z, 0.0f) + log1pf(expf(-fabsf(z)))) * 0.2f;
}
__device__ __forceinline__ float softplus_fast(float x) {
    return fmaxf(x, 0.0f) + __logf(1.0f + __expf(-fabsf(x)));
}

struct CloudW {
    const float* w0; const float* b0;
    const float* w1; const float* b1;
    const float* w2; const float* b2;
    const float* w3; const float* b3;
};
struct AllArgs {
    const float* xyz; const int* Z; const float* emb;
    CloudW c[2];
    const float *fc_w, *fc_b, *bn_g, *bn_b, *out_w, *out_b;
    float* out;
};

// ---------------- phase A: radial-MLP table build (blocks 0..63) ----------
__device__ void build_phase(const CloudW& cw, int cloud, int bx, int t,
                            float4* X0, float4* X1, float* red) {
    int tc = min(t, HID - 1);
    int pt0 = bx * PTS;
    bool ok  = (t < HID);
    bool act = (t < 160);

    float bas[PTS][3];
    const float hstep = RADIUS_F / (float)(MT - 1);
    #pragma unroll
    for (int p = 0; p < PTS; p++) {
        float r = (float)(pt0 + p) * hstep;
        #pragma unroll
        for (int j = 0; j < 3; j++) {
            float dd = (r - 1.5f * (float)j) * (1.0f / 1.5f);
            float cv = cosf(1.57079632679489662f * dd);
            bas[p][j] = (fabsf(dd) < 1.0f) ? cv * cv : 0.0f;
        }
    }

    // layer 0: 3 -> 150
    if (act) {
        float w0a = ok ? cw.w0[t]         : 0.0f;
        float w0b = ok ? cw.w0[HID + t]   : 0.0f;
        float w0c = ok ? cw.w0[2*HID + t] : 0.0f;
        float bb0 = ok ? cw.b0[t]         : 0.0f;
        float4 v;
        float* vp = (float*)&v;
        #pragma unroll
        for (int p = 0; p < PTS; p++) {
            float av = bb0;
            av = fmaf(bas[p][0], w0a, av);
            av = fmaf(bas[p][1], w0b, av);
            av = fmaf(bas[p][2], w0c, av);
            vp[p] = sp5(av);
        }
        X0[t] = v;
    }
    __syncthreads();

    // layers 1 & 2: 150 -> 150, register-prefetched weight chunks
    #pragma unroll
    for (int L = 0; L < 2; ++L) {
        const float* wp = (L == 0) ? cw.w1 : cw.w2;
        const float* bb = (L == 0) ? cw.b1 : cw.b2;
        const float4* S = (L == 0) ? X0 : X1;
        float4*       D = (L == 0) ? X1 : X0;

        if (act) {
            float bv = ok ? bb[t] : 0.0f;
            float acc0 = bv, acc1 = bv, acc2 = bv, acc3 = bv;

            float wbuf[CH];
            #pragma unroll
            for (int j = 0; j < CH; j++) wbuf[j] = wp[j*HID + tc];

            for (int k0 = 0; k0 < HID; k0 += CH) {   // 15 chunks
                float wn[CH];
                bool more = (k0 + CH < HID);
                #pragma unroll
                for (int j = 0; j < CH; j++)
                    wn[j] = more ? wp[(k0 + CH + j)*HID + tc] : 0.0f;
                #pragma unroll
                for (int j = 0; j < CH; j++) {
                    float4 x = S[k0 + j];
                    acc0 = fmaf(x.x, wbuf[j], acc0);
                    acc1 = fmaf(x.y, wbuf[j], acc1);
                    acc2 = fmaf(x.z, wbuf[j], acc2);
                    acc3 = fmaf(x.w, wbuf[j], acc3);
                }
                #pragma unroll
                for (int j = 0; j < CH; j++) wbuf[j] = wn[j];
            }
            float4 dv;
            dv.x = sp5(acc0); dv.y = sp5(acc1); dv.z = sp5(acc2); dv.w = sp5(acc3);
            D[t] = dv;
        }
        __syncthreads();
    }

    // layer 3: 150 -> 16, split k across 10 chunks of 15 (source is X0)
    if (act) {
        int o = t & 15, c = t >> 4;
        float a0 = 0.f, a1 = 0.f, a2 = 0.f, a3 = 0.f;
        #pragma unroll
        for (int kk = 0; kk < 15; kk++) {
            int k = c*15 + kk;
            float w = cw.w3[k*16 + o];
            float4 x = X0[k];
            a0 = fmaf(x.x, w, a0);
            a1 = fmaf(x.y, w, a1);
            a2 = fmaf(x.z, w, a2);
            a3 = fmaf(x.w, w, a3);
        }
        red[c*64 + 0*16 + o] = a0; red[c*64 + 1*16 + o] = a1;
        red[c*64 + 2*16 + o] = a2; red[c*64 + 3*16 + o] = a3;
    }
    __syncthreads();
    if (t < 16*PTS) {
        int o = t & 15, p = t >> 4;
        float s = cw.b3[o];
        #pragma unroll
        for (int c = 0; c < 10; c++) s += red[c*64 + p*16 + o];
        int pt = pt0 + p;
        int q = o >> 2, j = o & 3;
        g_tab2[cloud][pt*32 + q*8 + j] = s;            // this knot's k0 slot
        if (pt > 0)
            g_tab2[cloud][(pt-1)*32 + q*8 + 4 + j] = s; // previous knot's k1 slot
    }
}

// ---------------- phases B/C: pair convolution ----------------------------
template<int CLOUD>
__device__ void conv_phase(const float* __restrict__ xyz, int z, int ab, int t,
                           float4* sc, float4* sf, float* spp) {
    const float* feats = CLOUD ? g_f1 : g_feats0;
    const float* tab   = g_tab2[CLOUD];

    const float4* fz = (const float4*)(feats + (size_t)z * NA * 4);
    if (CLOUD == 0) {
        const float* xr = xyz + (size_t)z * NA * 3;
        for (int i = t; i < NAP; i += 256) {
            if (i < NA) {
                sc[i] = make_float4(xr[i*3+0], xr[i*3+1], xr[i*3+2], 0.f);
                sf[i] = fz[i];
            } else {
                sc[i] = make_float4(1.0e6f, 1.0e6f, 1.0e6f, 0.f);
                sf[i] = make_float4(0.f, 0.f, 0.f, 0.f);
            }
        }
    } else {
        for (int i = t; i < NAP; i += 256)
            sf[i] = (i < NA) ? fz[i] : make_float4(0.f, 0.f, 0.f, 0.f);
    }
    __syncthreads();

    int warp = t >> 5, lane = t & 31;
    int q = lane & 3;        // output channel
    int p = lane >> 2;       // pair slot (0..7)
    int a = ab * 8 + warp;
    const float uscale = (float)(MT - 1) / RADIUS_F;
    const float* tq = tab + q*8;
    float2* urow = g_uv + ((size_t)(z*NAP + a))*NAP;

    float acc = 0.0f;
    int cnt = 0;

    if (CLOUD == 0) {
        float4 ac = sc[a];
        #pragma unroll 4
        for (int it = 0; it < NAP/8; it++) {
            int b = p + it*8;
            float4 bc = sc[b];
            float dx = ac.x - bc.x;
            float dy = ac.y - bc.y;
            float dz = ac.z - bc.z;
            float d2 = fmaf(dx, dx, fmaf(dy, dy, dz*dz));
            bool hit = (d2 < 9.0f);
            float u = fminf(sqrtf(d2) * uscale, (float)(MT - 1) - 1e-3f);
            int i0 = (int)u;
            float tt = u - (float)i0;
            int off = hit ? i0*32 : -1;
            if ((lane & 3) == 0)
                urow[b] = make_float2(tt, __int_as_float(off));
            if (hit) {
                cnt++;
                const float* bp = tq + i0*32;
                float4 k0 = *(const float4*)bp;
                float4 k1 = *(const float4*)(bp + 4);
                float4 f = sf[b];
                float s0 = k0.x*f.x;
                s0 = fmaf(k0.y, f.y, s0);
                s0 = fmaf(k0.z, f.z, s0);
                s0 = fmaf(k0.w, f.w, s0);
                float s1 = k1.x*f.x;
                s1 = fmaf(k1.y, f.y, s1);
                s1 = fmaf(k1.z, f.z, s1);
                s1 = fmaf(k1.w, f.w, s1);
                acc += fmaf(tt, s1 - s0, s0);
            }
        }
    } else {
        #pragma unroll 4
        for (int it = 0; it < NAP/8; it++) {
            int b = p + it*8;
            float2 uv = urow[b];
            int off = __float_as_int(uv.y);
            if (off >= 0) {
                const float* bp = tq + off;
                float4 k0 = *(const float4*)bp;
                float4 k1 = *(const float4*)(bp + 4);
                float4 f = sf[b];
                float s0 = k0.x*f.x;
                s0 = fmaf(k0.y, f.y, s0);
                s0 = fmaf(k0.z, f.z, s0);
                s0 = fmaf(k0.w, f.w, s0);
                float s1 = k1.x*f.x;
                s1 = fmaf(k1.y, f.y, s1);
                s1 = fmaf(k1.z, f.z, s1);
                s1 = fmaf(k1.w, f.w, s1);
                acc += fmaf(uv.x, s1 - s0, s0);
            }
        }
    }

    // reduce over the 8 pair slots (lanes differing in bits 2..4)
    acc += __shfl_down_sync(0xffffffffu, acc, 16);
    acc += __shfl_down_sync(0xffffffffu, acc, 8);
    acc += __shfl_down_sync(0xffffffffu, acc, 4);

    if (CLOUD == 0) {
        cnt += __shfl_down_sync(0xffffffffu, cnt, 16);
        cnt += __shfl_down_sync(0xffffffffu, cnt, 8);
        cnt += __shfl_down_sync(0xffffffffu, cnt, 4);
        float nb = rsqrtf((float)max(cnt, 1));
        if (a < NA && lane == 0) g_nbinv[z*NA + a] = nb;
        if (a < NA && lane < 4)
            g_f1[((size_t)z*NA + a)*4 + lane] = acc * nb;
    } else {
        if (lane < 4) {
            float v1 = ((const float*)(sf + a))[q];
            float v2 = 0.0f;
            if (a < NA) {
                float nb = g_nbinv[z*NA + a];
                v2 = acc * nb;
            }
            spp[warp*8 + q]     = v1 * v1;
            spp[warp*8 + q + 4] = v2 * v2;
        }
        __syncthreads();
        if (t < 8) {
            float s = 0.0f;
            #pragma unroll
            for (int w = 0; w < 8; w++) s += spp[w*8 + t];
            g_part[z][ab][t] = s;
        }
    }
}

// ---------------- the single persistent kernel ----------------------------
__global__ void __launch_bounds__(256, 4) k_all(AllArgs A) {
    __shared__ float4 s_sc[NAP];
    __shared__ float4 s_sf[NAP];
    __shared__ float  s_misc[640];

    int blk = blockIdx.x;
    int t   = threadIdx.x;

    // ---- phase A: table build (blocks 0..63) + embedding gather (64..81)
    if (blk < 64) {
        build_phase(A.c[blk >> 5], blk >> 5, blk & 31, t,
                    s_sc, s_sf, s_misc);
    } else if (blk < 82) {
        int i = (blk - 64)*256 + t;
        if (i < BB*NA) {
            int zi = A.Z[i];
            float4 e = *(const float4*)(A.emb + zi*4);
            *(float4*)(g_feats0 + i*4) = e;
        }
    }
    grid_sync();

    // ---- phase B: conv cloud 0
    {
        int z = blk % BB, ab = blk / BB;
        conv_phase<0>(A.xyz, z, ab, t, s_sc, s_sf, s_misc);
    }
    grid_sync();

    // ---- phase C: conv cloud 1 + fused pool partials
    {
        int z = blk % BB, ab = blk / BB;
        conv_phase<1>(A.xyz, z, ab, t, s_sc, s_sf, s_misc);
    }
    grid_sync();

    // ---- phase D: head (blocks 0..7): pool-reduce + FC + batchnorm
    if (blk < 8) {
        float* pooled = s_misc;          // [16][8]
        float* smw    = s_misc + 128;    // [8 warps][4 zg][4 i]
        int lane = t & 31, warp = t >> 5;

        if (t < 128) {                   // 16 z x 8 j
            int z = t >> 3, j = t & 7;
            float s = 0.0f;
            #pragma unroll
            for (int c = 0; c < NBLK; c++) s += g_part[z][c][j];
            pooled[z*8 + j] = sqrtf(s);
        }
        __syncthreads();

        int f  = blk*64 + (t >> 2);      // 8 blocks x 64 features
        int zg = t & 3;                  // my 4 batches: z = zg*4 + i
        float bias = A.fc_b[f];
        float w0 = A.fc_w[0*FF + f], w1 = A.fc_w[1*FF + f];
        float w2 = A.fc_w[2*FF + f], w3 = A.fc_w[3*FF + f];
        float w4 = A.fc_w[4*FF + f], w5 = A.fc_w[5*FF + f];
        float w6 = A.fc_w[6*FF + f], w7 = A.fc_w[7*FF + f];

        float hv[4];
        float msum = 0.0f;
        #pragma unroll
        for (int i = 0; i < 4; i++) {
            int z = zg*4 + i;
            float av = bias;
            av = fmaf(pooled[z*8+0], w0, av);
            av = fmaf(pooled[z*8+1], w1, av);
            av = fmaf(pooled[z*8+2], w2, av);
            av = fmaf(pooled[z*8+3], w3, av);
            av = fmaf(pooled[z*8+4], w4, av);
            av = fmaf(pooled[z*8+5], w5, av);
            av = fmaf(pooled[z*8+6], w6, av);
            av = fmaf(pooled[z*8+7], w7, av);
            hv[i] = softplus_fast(av);
            msum += hv[i];
        }
        msum += __shfl_xor_sync(0xffffffffu, msum, 1);
        msum += __shfl_xor_sync(0xffffffffu, msum, 2);
        float m = msum * (1.0f / (float)BB);

        float vsum = 0.0f;
        #pragma unroll
        for (int i = 0; i < 4; i++) { float d = hv[i] - m; vsum += d*d; }
        vsum += __shfl_xor_sync(0xffffffffu, vsum, 1);
        vsum += __shfl_xor_sync(0xffffffffu, vsum, 2);
        float v = vsum * (1.0f / (float)BB);

        float sc = rsqrtf(v + 1e-5f) * A.bn_g[f];
        float bo = A.bn_b[f];
        float ww = A.out_w[f];

        float acc[4];
        #pragma unroll
        for (int i = 0; i < 4; i++)
            acc[i] = softplus_fast((hv[i] - m) * sc + bo) * ww;

        #pragma unroll
        for (int i = 0; i < 4; i++) {
            acc[i] += __shfl_down_sync(0xffffffffu, acc[i], 16);
            acc[i] += __shfl_down_sync(0xffffffffu, acc[i], 8);
            acc[i] += __shfl_down_sync(0xffffffffu, acc[i], 4);
        }
        if (lane < 4) {
            #pragma unroll
            for (int i = 0; i < 4; i++) smw[warp*16 + lane*4 + i] = acc[i];
        }
        __syncthreads();
        if (t < BB) {
            int zg2 = t >> 2, i2 = t & 3;
            float s = 0.0f;
            #pragma unroll
            for (int w = 0; w < 8; w++) s += smw[w*16 + zg2*4 + i2];
            g_hpart[blk][t] = s;
        }
    }
    grid_sync();

    // ---- phase E: combine + sigmoid (block 0)
    if (blk == 0 && t < BB) {
        float s = A.out_b[0];
        #pragma unroll
        for (int b = 0; b < 8; b++) s += g_hpart[b][t];
        A.out[t] = 1.0f / (1.0f + __expf(-s));
    }
}

// ---------------- launch --------------------------------------------------
extern "C" void kernel_launch(void* const* d_in, const int* in_sizes, int n_in,
                              void* d_out, int out_size) {
    AllArgs A;
    A.xyz = (const float*)d_in[0];
    A.Z   = (const int*)  d_in[1];
    A.emb = (const float*)d_in[2];
    A.c[0].w0 = (const float*)d_in[3];  A.c[0].b0 = (const float*)d_in[4];
    A.c[0].w1 = (const float*)d_in[5];  A.c[0].b1 = (const float*)d_in[6];
    A.c[0].w2 = (const float*)d_in[7];  A.c[0].b2 = (const float*)d_in[8];
    A.c[0].w3 = (const float*)d_in[9];  A.c[0].b3 = (const float*)d_in[10];
    A.c[1].w0 = (const float*)d_in[11]; A.c[1].b0 = (const float*)d_in[12];
    A.c[1].w1 = (const float*)d_in[13]; A.c[1].b1 = (const float*)d_in[14];
    A.c[1].w2 = (const float*)d_in[15]; A.c[1].b2 = (const float*)d_in[16];
    A.c[1].w3 = (const float*)d_in[17]; A.c[1].b3 = (const float*)d_in[18];
    A.fc_w  = (const float*)d_in[19];
    A.fc_b  = (const float*)d_in[20];
    A.bn_g  = (const float*)d_in[21];
    A.bn_b  = (const float*)d_in[22];
    A.out_w = (const float*)d_in[23];
    A.out_b = (const float*)d_in[24];
    A.out   = (float*)d_out;

    k_all<<<NBLOCKS, 256>>>(A);
}

// round 16
// speedup vs baseline: 1.0786x; 1.0786x over previous
#include <cuda_runtime.h>
#include <math.h>

#define BB      16
#define NA      286
#define NAP     288       // padded atom count (multiple of 8)
#define HID     150
#define FF      512
#define RADIUS_F 3.0f
#define MT      128       // table knots per cloud
#define PTS     4         // points per build block
#define CH      10        // k-chunk (prefetch depth) in build
#define NBLK    (NAP/8)   // conv tiles per batch (36)
#define NBLOCKS (NBLK*BB) // 576 conv blocks

// ---------------- scratch (device globals; no allocation allowed) ----------
__device__ __align__(16) float g_feats0[BB*NA*4];
__device__ __align__(16) float g_f1[BB*NA*4];
// paired-knot table: row i holds {K_i[q][0..3], K_{i+1}[q][0..3]} for q=0..3
__device__ __align__(16) float g_tab2[2][MT*32];
__device__ float g_nbinv[BB*NA];
// per-pair replay: {tt, offset-as-int-bits}; offset<0 => miss
__device__ __align__(16) float2 g_uv[(size_t)BB*NAP*NAP];
__device__ float g_part[BB][NBLK][8];    // per-block pooled partial sums
__device__ float g_hpart[8][BB];         // per-head-slot output partials
// ticket state: g_done is a monotonically-increasing generation (survives
// graph replays); g_cnt / g_cnt2 are reset by their last consumer each run.
__device__ int          g_cnt;
__device__ int          g_cnt2;
__device__ volatile int g_done;

__device__ __forceinline__ float sp5(float x) {
    float z = 5.0f * x;
    return (fmaxf(z, 0.0f) + log1pf(expf(-fabsf(z)))) * 0.2f;
}
__device__ __forceinline__ float softplus_fast(float x) {
    return fmaxf(x, 0.0f) + __logf(1.0f + __expf(-fabsf(x)));
}

// ---------------- 1. radial-MLP table build + embedded gather -------------
struct CloudW {
    const float* w0; const float* b0;
    const float* w1; const float* b1;
    const float* w2; const float* b2;
    const float* w3; const float* b3;
};
struct BuildArgs { CloudW c[2]; };

__global__ void __launch_bounds__(HID + 10) k_build(BuildArgs args,
                                                    const int* __restrict__ Z,
                                                    const float* __restrict__ emb) {
    int cloud = blockIdx.y;
    int t = threadIdx.x;                 // 0..159

    if (cloud == 2) {                    // embedding-gather plane
        int i = blockIdx.x * (HID + 10) + t;
        if (i < BB*NA) {
            int zi = Z[i];
            float4 e = *(const float4*)(emb + zi*4);
            *(float4*)(g_feats0 + i*4) = e;
        }
        return;
    }

    CloudW cw = args.c[cloud];
    int tc = min(t, HID - 1);
    int pt0 = blockIdx.x * PTS;

    __shared__ float4 X0[HID + 10];
    __shared__ float4 X1[HID + 10];
    __shared__ float red[10][PTS][16];

    bool ok = (t < HID);

    float bas[PTS][3];
    const float hstep = RADIUS_F / (float)(MT - 1);
    #pragma unroll
    for (int p = 0; p < PTS; p++) {
        float r = (float)(pt0 + p) * hstep;
        #pragma unroll
        for (int j = 0; j < 3; j++) {
            float dd = (r - 1.5f * (float)j) * (1.0f / 1.5f);
            float cv = cosf(1.57079632679489662f * dd);
            bas[p][j] = (fabsf(dd) < 1.0f) ? cv * cv : 0.0f;
        }
    }

    // layer 0: 3 -> 150
    {
        float w0a = ok ? cw.w0[t]         : 0.0f;
        float w0b = ok ? cw.w0[HID + t]   : 0.0f;
        float w0c = ok ? cw.w0[2*HID + t] : 0.0f;
        float bb0 = ok ? cw.b0[t]         : 0.0f;
        float4 v;
        float* vp = (float*)&v;
        #pragma unroll
        for (int p = 0; p < PTS; p++) {
            float av = bb0;
            av = fmaf(bas[p][0], w0a, av);
            av = fmaf(bas[p][1], w0b, av);
            av = fmaf(bas[p][2], w0c, av);
            vp[p] = sp5(av);
        }
        X0[t] = v;
    }
    __syncthreads();

    // layers 1 & 2: 150 -> 150, register-prefetched weight chunks
    #pragma unroll
    for (int L = 0; L < 2; ++L) {
        const float* wp = (L == 0) ? cw.w1 : cw.w2;
        const float* bb = (L == 0) ? cw.b1 : cw.b2;
        const float4* S = (L == 0) ? X0 : X1;
        float4*       D = (L == 0) ? X1 : X0;

        float bv = ok ? bb[t] : 0.0f;
        float acc0 = bv, acc1 = bv, acc2 = bv, acc3 = bv;

        float wbuf[CH];
        #pragma unroll
        for (int j = 0; j < CH; j++) wbuf[j] = wp[j*HID + tc];

        for (int k0 = 0; k0 < HID; k0 += CH) {   // 15 chunks
            float wn[CH];
            bool more = (k0 + CH < HID);
            #pragma unroll
            for (int j = 0; j < CH; j++)
                wn[j] = more ? wp[(k0 + CH + j)*HID + tc] : 0.0f;
            #pragma unroll
            for (int j = 0; j < CH; j++) {
                float4 x = S[k0 + j];
                acc0 = fmaf(x.x, wbuf[j], acc0);
                acc1 = fmaf(x.y, wbuf[j], acc1);
                acc2 = fmaf(x.z, wbuf[j], acc2);
                acc3 = fmaf(x.w, wbuf[j], acc3);
            }
            #pragma unroll
            for (int j = 0; j < CH; j++) wbuf[j] = wn[j];
        }
        float4 dv;
        dv.x = sp5(acc0); dv.y = sp5(acc1); dv.z = sp5(acc2); dv.w = sp5(acc3);
        D[t] = dv;
        __syncthreads();
    }

    // layer 3: 150 -> 16, split k across 10 chunks of 15 (source is X0)
    {
        int o = t & 15, c = t >> 4;
        float a0 = 0.f, a1 = 0.f, a2 = 0.f, a3 = 0.f;
        #pragma unroll
        for (int kk = 0; kk < 15; kk++) {
            int k = c*15 + kk;
            float w = cw.w3[k*16 + o];
            float4 x = X0[k];
            a0 = fmaf(x.x, w, a0);
            a1 = fmaf(x.y, w, a1);
            a2 = fmaf(x.z, w, a2);
            a3 = fmaf(x.w, w, a3);
        }
        red[c][0][o] = a0; red[c][1][o] = a1;
        red[c][2][o] = a2; red[c][3][o] = a3;
    }
    __syncthreads();
    if (t < 16*PTS) {
        int o = t & 15, p = t >> 4;
        float s = cw.b3[o];
        #pragma unroll
        for (int c = 0; c < 10; c++) s += red[c][p][o];
        int pt = pt0 + p;
        int q = o >> 2, j = o & 3;
        g_tab2[cloud][pt*32 + q*8 + j] = s;            // this knot's k0 slot
        if (pt > 0)
            g_tab2[cloud][(pt-1)*32 + q*8 + 4 + j] = s; // previous knot's k1 slot
    }
}

// ---------------- 2. conv cloud 0 (unchanged R14 body) --------------------
__global__ void __launch_bounds__(256) k_conv0(const float* __restrict__ xyz) {
    int z = blockIdx.y;
    const float* tab = g_tab2[0];

    __shared__ float4 sc[NAP];
    __shared__ float4 sf[NAP];
    const float4* fz = (const float4*)(g_feats0 + (size_t)z * NA * 4);
    const float* xr = xyz + (size_t)z * NA * 3;
    for (int i = threadIdx.x; i < NAP; i += 256) {
        if (i < NA) {
            sc[i] = make_float4(xr[i*3+0], xr[i*3+1], xr[i*3+2], 0.f);
            sf[i] = fz[i];
        } else {
            sc[i] = make_float4(1.0e6f, 1.0e6f, 1.0e6f, 0.f);
            sf[i] = make_float4(0.f, 0.f, 0.f, 0.f);
        }
    }
    __syncthreads();

    int warp = threadIdx.x >> 5, lane = threadIdx.x & 31;
    int q = lane & 3;
    int p = lane >> 2;
    int a = blockIdx.x * 8 + warp;
    const float uscale = (float)(MT - 1) / RADIUS_F;
    const float* tq = tab + q*8;
    float2* urow = g_uv + ((size_t)(z*NAP + a))*NAP;

    float acc = 0.0f;
    int cnt = 0;
    float4 ac = sc[a];
    #pragma unroll 4
    for (int it = 0; it < NAP/8; it++) {
        int b = p + it*8;
        float4 bc = sc[b];
        float dx = ac.x - bc.x;
        float dy = ac.y - bc.y;
        float dz = ac.z - bc.z;
        float d2 = fmaf(dx, dx, fmaf(dy, dy, dz*dz));
        bool hit = (d2 < 9.0f);
        float u = fminf(sqrtf(d2) * uscale, (float)(MT - 1) - 1e-3f);
        int i0 = (int)u;
        float tt = u - (float)i0;
        int off = hit ? i0*32 : -1;
        if ((lane & 3) == 0)
            urow[b] = make_float2(tt, __int_as_float(off));
        if (hit) {
            cnt++;
            const float* bp = tq + i0*32;
            float4 k0 = *(const float4*)bp;
            float4 k1 = *(const float4*)(bp + 4);
            float4 f = sf[b];
            float s0 = k0.x*f.x;
            s0 = fmaf(k0.y, f.y, s0);
            s0 = fmaf(k0.z, f.z, s0);
            s0 = fmaf(k0.w, f.w, s0);
            float s1 = k1.x*f.x;
            s1 = fmaf(k1.y, f.y, s1);
            s1 = fmaf(k1.z, f.z, s1);
            s1 = fmaf(k1.w, f.w, s1);
            acc += fmaf(tt, s1 - s0, s0);
        }
    }
    acc += __shfl_down_sync(0xffffffffu, acc, 16);
    acc += __shfl_down_sync(0xffffffffu, acc, 8);
    acc += __shfl_down_sync(0xffffffffu, acc, 4);
    cnt += __shfl_down_sync(0xffffffffu, cnt, 16);
    cnt += __shfl_down_sync(0xffffffffu, cnt, 8);
    cnt += __shfl_down_sync(0xffffffffu, cnt, 4);
    float nb = rsqrtf((float)max(cnt, 1));
    if (a < NA && lane == 0) g_nbinv[z*NA + a] = nb;
    if (a < NA && lane < 4)
        g_f1[((size_t)z*NA + a)*4 + lane] = acc * nb;
}

// ---------------- 3. conv cloud 1 + pool + (tail) head + sigmoid ----------
// Conv body identical to R14's k_conv<1>. After writing g_part, blocks take
// a ticket; the LAST 8 tickets become head blocks (feature slot = ticket -
// (NBLOCKS-8)); the last ticket releases g_done (generation) and resets the
// counter for graph replay. Head blocks spin only after finishing their own
// conv work (all 576 blocks are wave-1 resident at >=4 blocks/SM).
__global__ void __launch_bounds__(256, 4) k_conv1h(const float* __restrict__ xyz,
                                                   const float* __restrict__ fcw,
                                                   const float* __restrict__ fcb,
                                                   const float* __restrict__ bng,
                                                   const float* __restrict__ bnb,
                                                   const float* __restrict__ ow,
                                                   const float* __restrict__ ob,
                                                   float* __restrict__ out) {
    int z = blockIdx.y;
    int ab = blockIdx.x;
    int t = threadIdx.x;
    const float* tab = g_tab2[1];

    __shared__ float4 sf[NAP];
    __shared__ float  s_misc[256];       // spp / pooled+smw reuse
    __shared__ int    s_gen, s_ticket;

    if (t == 0) s_gen = g_done;          // entry generation (safe: release
                                         // needs all 576 convs done)
    const float4* fz = (const float4*)(g_f1 + (size_t)z * NA * 4);
    for (int i = t; i < NAP; i += 256)
        sf[i] = (i < NA) ? fz[i] : make_float4(0.f, 0.f, 0.f, 0.f);
    __syncthreads();

    int warp = t >> 5, lane = t & 31;
    int q = lane & 3;
    int p = lane >> 2;
    int a = ab * 8 + warp;
    const float* tq = tab + q*8;
    const float2* urow = g_uv + ((size_t)(z*NAP + a))*NAP;

    float acc = 0.0f;
    #pragma unroll 4
    for (int it = 0; it < NAP/8; it++) {
        int b = p + it*8;
        float2 uv = urow[b];
        int off = __float_as_int(uv.y);
        if (off >= 0) {
            const float* bp = tq + off;
            float4 k0 = *(const float4*)bp;
            float4 k1 = *(const float4*)(bp + 4);
            float4 f = sf[b];
            float s0 = k0.x*f.x;
            s0 = fmaf(k0.y, f.y, s0);
            s0 = fmaf(k0.z, f.z, s0);
            s0 = fmaf(k0.w, f.w, s0);
            float s1 = k1.x*f.x;
            s1 = fmaf(k1.y, f.y, s1);
            s1 = fmaf(k1.z, f.z, s1);
            s1 = fmaf(k1.w, f.w, s1);
            acc += fmaf(uv.x, s1 - s0, s0);
        }
    }
    acc += __shfl_down_sync(0xffffffffu, acc, 16);
    acc += __shfl_down_sync(0xffffffffu, acc, 8);
    acc += __shfl_down_sync(0xffffffffu, acc, 4);

    if (lane < 4) {
        float v1 = ((const float*)(sf + a))[q];
        float v2 = 0.0f;
        if (a < NA) {
            float nb = g_nbinv[z*NA + a];
            v2 = acc * nb;
        }
        s_misc[warp*8 + q]     = v1 * v1;
        s_misc[warp*8 + q + 4] = v2 * v2;
    }
    __syncthreads();
    if (t < 8) {
        float s = 0.0f;
        #pragma unroll
        for (int w = 0; w < 8; w++) s += s_misc[w*8 + t];
        g_part[z][ab][t] = s;
    }
    __threadfence();
    __syncthreads();
    if (t == 0) s_ticket = atomicAdd(&g_cnt, 1);
    __syncthreads();
    int ticket = s_ticket;

    if (ticket == NBLOCKS - 1) {         // all conv work done
        if (t == 0) {
            g_cnt = 0;                   // reset for next graph replay
            __threadfence();
            g_done = s_gen + 1;          // release
        }
    }
    if (ticket < NBLOCKS - 8) return;    // not a head block

    // ---- head: this block owns features slot*64 .. slot*64+63
    int slot = ticket - (NBLOCKS - 8);
    if (t == 0) {
        while (g_done == s_gen) __nanosleep(32);
    }
    __syncthreads();
    __threadfence();                     // acquire: make all g_part visible

    float* pooled = s_misc;              // [16][8]
    {
        __syncthreads();                 // s_misc reuse
        if (t < 128) {                   // 16 z x 8 j
            int zz = t >> 3, j = t & 7;
            float s = 0.0f;
            #pragma unroll
            for (int c = 0; c < NBLK; c++) s += g_part[zz][c][j];
            pooled[zz*8 + j] = sqrtf(s);
        }
        __syncthreads();
    }

    int f  = slot*64 + (t >> 2);
    int zg = t & 3;                      // my 4 batches: z = zg*4 + i
    float bias = fcb[f];
    float w0 = fcw[0*FF + f], w1 = fcw[1*FF + f];
    float w2 = fcw[2*FF + f], w3 = fcw[3*FF + f];
    float w4 = fcw[4*FF + f], w5 = fcw[5*FF + f];
    float w6 = fcw[6*FF + f], w7 = fcw[7*FF + f];

    float hv[4];
    float msum = 0.0f;
    #pragma unroll
    for (int i = 0; i < 4; i++) {
        int zz = zg*4 + i;
        float av = bias;
        av = fmaf(pooled[zz*8+0], w0, av);
        av = fmaf(pooled[zz*8+1], w1, av);
        av = fmaf(pooled[zz*8+2], w2, av);
        av = fmaf(pooled[zz*8+3], w3, av);
        av = fmaf(pooled[zz*8+4], w4, av);
        av = fmaf(pooled[zz*8+5], w5, av);
        av = fmaf(pooled[zz*8+6], w6, av);
        av = fmaf(pooled[zz*8+7], w7, av);
        hv[i] = softplus_fast(av);
        msum += hv[i];
    }
    msum += __shfl_xor_sync(0xffffffffu, msum, 1);
    msum += __shfl_xor_sync(0xffffffffu, msum, 2);
    float m = msum * (1.0f / (float)BB);

    float vsum = 0.0f;
    #pragma unroll
    for (int i = 0; i < 4; i++) { float d = hv[i] - m; vsum += d*d; }
    vsum += __shfl_xor_sync(0xffffffffu, vsum, 1);
    vsum += __shfl_xor_sync(0xffffffffu, vsum, 2);
    float v = vsum * (1.0f / (float)BB);

    float sc = rsqrtf(v + 1e-5f) * bng[f];
    float bo = bnb[f];
    float ww = ow[f];

    float hacc[4];
    #pragma unroll
    for (int i = 0; i < 4; i++)
        hacc[i] = softplus_fast((hv[i] - m) * sc + bo) * ww;

    #pragma unroll
    for (int i = 0; i < 4; i++) {
        hacc[i] += __shfl_down_sync(0xffffffffu, hacc[i], 16);
        hacc[i] += __shfl_down_sync(0xffffffffu, hacc[i], 8);
        hacc[i] += __shfl_down_sync(0xffffffffu, hacc[i], 4);
    }
    __syncthreads();                     // s_misc reuse: smw
    float* smw = s_misc + 128;           // [8 warps][4 zg][4 i]
    if (lane < 4) {
        #pragma unroll
        for (int i = 0; i < 4; i++) smw[warp*16 + lane*4 + i] = hacc[i];
    }
    __syncthreads();
    if (t < BB) {
        int zg2 = t >> 2, i2 = t & 3;
        float s = 0.0f;
        #pragma unroll
        for (int w = 0; w < 8; w++) s += smw[w*16 + zg2*4 + i2];
        g_hpart[slot][t] = s;
    }
    __threadfence();
    __syncthreads();
    if (t == 0) s_ticket = atomicAdd(&g_cnt2, 1);
    __syncthreads();

    if (s_ticket == 7) {                 // last head block: combine + sigmoid
        if (t == 0) g_cnt2 = 0;          // reset for next replay
        __threadfence();
        if (t < BB) {
            float s = ob[0];
            #pragma unroll
            for (int b = 0; b < 8; b++) s += g_hpart[b][t];
            out[t] = 1.0f / (1.0f + __expf(-s));
        }
    }
}

// ---------------- launch --------------------------------------------------
extern "C" void kernel_launch(void* const* d_in, const int* in_sizes, int n_in,
                              void* d_out, int out_size) {
    const float* xyz   = (const float*)d_in[0];
    const int*   Z     = (const int*)  d_in[1];
    const float* emb   = (const float*)d_in[2];
    BuildArgs ba;
    ba.c[0].w0 = (const float*)d_in[3];  ba.c[0].b0 = (const float*)d_in[4];
    ba.c[0].w1 = (const float*)d_in[5];  ba.c[0].b1 = (const float*)d_in[6];
    ba.c[0].w2 = (const float*)d_in[7];  ba.c[0].b2 = (const float*)d_in[8];
    ba.c[0].w3 = (const float*)d_in[9];  ba.c[0].b3 = (const float*)d_in[10];
    ba.c[1].w0 = (const float*)d_in[11]; ba.c[1].b0 = (const float*)d_in[12];
    ba.c[1].w1 = (const float*)d_in[13]; ba.c[1].b1 = (const float*)d_in[14];
    ba.c[1].w2 = (const float*)d_in[15]; ba.c[1].b2 = (const float*)d_in[16];
    ba.c[1].w3 = (const float*)d_in[17]; ba.c[1].b3 = (const float*)d_in[18];
    const float* fc_w  = (const float*)d_in[19];
    const float* fc_b  = (const float*)d_in[20];
    const float* bn_g  = (const float*)d_in[21];
    const float* bn_b  = (const float*)d_in[22];
    const float* out_w = (const float*)d_in[23];
    const float* out_b = (const float*)d_in[24];
    float* out = (float*)d_out;

    // y planes: 0,1 = table build per cloud; 2 = embedding gather
    k_build<<<dim3(MT / PTS, 3), HID + 10>>>(ba, Z, emb);

    dim3 cg(NBLK, BB);
    k_conv0<<<cg, 256>>>(xyz);
    k_conv1h<<<cg, 256>>>(xyz, fc_w, fc_b, bn_g, bn_b, out_w, out_b, out);
}

// round 17
// speedup vs baseline: 1.1472x; 1.0636x over previous
#include <cuda_runtime.h>
#include <math.h>

#define BB      16
#define NA      286
#define NAP     288       // padded atom count (multiple of 8)
#define HID     150
#define FF      512
#define RADIUS_F 3.0f
#define MT      128       // table knots per cloud
#define PTS     4         // points per build block
#define CH      25        // k-chunk (prefetch depth) in build: 6 chunks/layer
#define NBLK    (NAP/8)   // conv blocks per batch (36)

// ---------------- scratch (device globals; no allocation allowed) ----------
__device__ __align__(16) float g_feats0[BB*NA*4];
__device__ __align__(16) float g_f1[BB*NA*4];
// paired-knot table: row i holds {K_i[q][0..3], K_{i+1}[q][0..3]} for q=0..3
__device__ __align__(16) float g_tab2[2][MT*32];
__device__ float g_nbinv[BB*NA];
// per-pair replay: {tt, offset-as-int-bits}; offset<0 => miss
__device__ __align__(16) float2 g_uv[(size_t)BB*NAP*NAP];
__device__ float g_part[BB][NBLK][8];    // per-block pooled partial sums
__device__ float g_hpart[4][BB];         // per-head-block output partials

__device__ __forceinline__ float sp5(float x) {
    float z = 5.0f * x;
    return (fmaxf(z, 0.0f) + log1pf(expf(-fabsf(z)))) * 0.2f;
}
__device__ __forceinline__ float softplus_fast(float x) {
    return fmaxf(x, 0.0f) + __logf(1.0f + __expf(-fabsf(x)));
}

// ---------------- 1. radial-MLP table build + embedded gather -------------
struct CloudW {
    const float* w0; const float* b0;
    const float* w1; const float* b1;
    const float* w2; const float* b2;
    const float* w3; const float* b3;
};
struct BuildArgs { CloudW c[2]; };

__global__ void __launch_bounds__(HID + 10) k_build(BuildArgs args,
                                                    const int* __restrict__ Z,
                                                    const float* __restrict__ emb) {
    int cloud = blockIdx.y;
    int t = threadIdx.x;                 // 0..159

    if (cloud == 2) {                    // embedding-gather plane
        int i = blockIdx.x * (HID + 10) + t;
        if (i < BB*NA) {
            int zi = Z[i];
            float4 e = *(const float4*)(emb + zi*4);
            *(float4*)(g_feats0 + i*4) = e;
        }
        return;
    }

    CloudW cw = args.c[cloud];
    int tc = min(t, HID - 1);
    int pt0 = blockIdx.x * PTS;

    __shared__ float4 X0[HID + 10];
    __shared__ float4 X1[HID + 10];
    __shared__ float red[10][PTS][16];

    bool ok = (t < HID);

    float bas[PTS][3];
    const float hstep = RADIUS_F / (float)(MT - 1);
    #pragma unroll
    for (int p = 0; p < PTS; p++) {
        float r = (float)(pt0 + p) * hstep;
        #pragma unroll
        for (int j = 0; j < 3; j++) {
            float dd = (r - 1.5f * (float)j) * (1.0f / 1.5f);
            float cv = cosf(1.57079632679489662f * dd);
            bas[p][j] = (fabsf(dd) < 1.0f) ? cv * cv : 0.0f;
        }
    }

    // layer 0: 3 -> 150
    {
        float w0a = ok ? cw.w0[t]         : 0.0f;
        float w0b = ok ? cw.w0[HID + t]   : 0.0f;
        float w0c = ok ? cw.w0[2*HID + t] : 0.0f;
        float bb0 = ok ? cw.b0[t]         : 0.0f;
        float4 v;
        float* vp = (float*)&v;
        #pragma unroll
        for (int p = 0; p < PTS; p++) {
            float av = bb0;
            av = fmaf(bas[p][0], w0a, av);
            av = fmaf(bas[p][1], w0b, av);
            av = fmaf(bas[p][2], w0c, av);
            vp[p] = sp5(av);
        }
        X0[t] = v;
    }
    __syncthreads();

    // layers 1 & 2: 150 -> 150, deep register-prefetched weight chunks
    #pragma unroll
    for (int L = 0; L < 2; ++L) {
        const float* wp = (L == 0) ? cw.w1 : cw.w2;
        const float* bb = (L == 0) ? cw.b1 : cw.b2;
        const float4* S = (L == 0) ? X0 : X1;
        float4*       D = (L == 0) ? X1 : X0;

        float bv = ok ? bb[t] : 0.0f;
        float acc0 = bv, acc1 = bv, acc2 = bv, acc3 = bv;

        float wbuf[CH];
        #pragma unroll
        for (int j = 0; j < CH; j++) wbuf[j] = wp[j*HID + tc];

        for (int k0 = 0; k0 < HID; k0 += CH) {   // 6 chunks
            float wn[CH];
            bool more = (k0 + CH < HID);
            #pragma unroll
            for (int j = 0; j < CH; j++)
                wn[j] = more ? wp[(k0 + CH + j)*HID + tc] : 0.0f;
            #pragma unroll
            for (int j = 0; j < CH; j++) {
                float4 x = S[k0 + j];
                acc0 = fmaf(x.x, wbuf[j], acc0);
                acc1 = fmaf(x.y, wbuf[j], acc1);
                acc2 = fmaf(x.z, wbuf[j], acc2);
                acc3 = fmaf(x.w, wbuf[j], acc3);
            }
            #pragma unroll
            for (int j = 0; j < CH; j++) wbuf[j] = wn[j];
        }
        float4 dv;
        dv.x = sp5(acc0); dv.y = sp5(acc1); dv.z = sp5(acc2); dv.w = sp5(acc3);
        D[t] = dv;
        __syncthreads();
    }

    // layer 3: 150 -> 16, split k across 10 chunks of 15 (source is X0)
    {
        int o = t & 15, c = t >> 4;
        float a0 = 0.f, a1 = 0.f, a2 = 0.f, a3 = 0.f;
        #pragma unroll
        for (int kk = 0; kk < 15; kk++) {
            int k = c*15 + kk;
            float w = cw.w3[k*16 + o];
            float4 x = X0[k];
            a0 = fmaf(x.x, w, a0);
            a1 = fmaf(x.y, w, a1);
            a2 = fmaf(x.z, w, a2);
            a3 = fmaf(x.w, w, a3);
        }
        red[c][0][o] = a0; red[c][1][o] = a1;
        red[c][2][o] = a2; red[c][3][o] = a3;
    }
    __syncthreads();
    if (t < 16*PTS) {
        int o = t & 15, p = t >> 4;
        float s = cw.b3[o];
        #pragma unroll
        for (int c = 0; c < 10; c++) s += red[c][p][o];
        int pt = pt0 + p;
        int q = o >> 2, j = o & 3;
        g_tab2[cloud][pt*32 + q*8 + j] = s;            // this knot's k0 slot
        if (pt > 0)
            g_tab2[cloud][(pt-1)*32 + q*8 + 4 + j] = s; // previous knot's k1 slot
    }
}

// ---------------- 2. pair convolution ------------------------------------
// grid (NBLK, BB), 256 threads, 1 atom per warp.
// CLOUD 0: computes geometry, stores per-pair replay {tt, offset} to g_uv,
//          writes f1 and nbinv.
// CLOUD 1: replays geometry from g_uv, fuses the L2-pool partial sums.
template<int CLOUD>
__global__ void __launch_bounds__(256) k_conv(const float* __restrict__ xyz) {
    int z = blockIdx.y;
    const float* feats = CLOUD ? g_f1 : g_feats0;
    const float* tab   = g_tab2[CLOUD];

    __shared__ float4 sc[CLOUD ? 1 : NAP];
    __shared__ float4 sf[NAP];
    __shared__ float  spp[8][8];
    const float4* fz = (const float4*)(feats + (size_t)z * NA * 4);
    if (CLOUD == 0) {
        const float* xr = xyz + (size_t)z * NA * 3;
        for (int i = threadIdx.x; i < NAP; i += 256) {
            if (i < NA) {
                sc[i] = make_float4(xr[i*3+0], xr[i*3+1], xr[i*3+2], 0.f);
                sf[i] = fz[i];
            } else {
                sc[i] = make_float4(1.0e6f, 1.0e6f, 1.0e6f, 0.f);
                sf[i] = make_float4(0.f, 0.f, 0.f, 0.f);
            }
        }
    } else {
        for (int i = threadIdx.x; i < NAP; i += 256)
            sf[i] = (i < NA) ? fz[i] : make_float4(0.f, 0.f, 0.f, 0.f);
    }
    __syncthreads();

    int warp = threadIdx.x >> 5, lane = threadIdx.x & 31;
    int q = lane & 3;        // output channel
    int p = lane >> 2;       // pair slot (0..7)
    int a = blockIdx.x * 8 + warp;
    const float uscale = (float)(MT - 1) / RADIUS_F;
    const float* tq = tab + q*8;
    float2* urow = g_uv + ((size_t)(z*NAP + a))*NAP;

    float acc = 0.0f;
    int cnt = 0;

    if (CLOUD == 0) {
        float4 ac = sc[a];
        #pragma unroll 4
        for (int it = 0; it < NAP/8; it++) {
            int b = p + it*8;
            float4 bc = sc[b];
            float dx = ac.x - bc.x;
            float dy = ac.y - bc.y;
            float dz = ac.z - bc.z;
            float d2 = fmaf(dx, dx, fmaf(dy, dy, dz*dz));
            bool hit = (d2 < 9.0f);
            float u = fminf(sqrtf(d2) * uscale, (float)(MT - 1) - 1e-3f);
            int i0 = (int)u;
            float tt = u - (float)i0;
            int off = hit ? i0*32 : -1;
            if ((lane & 3) == 0)
                urow[b] = make_float2(tt, __int_as_float(off));
            if (hit) {
                cnt++;
                const float* bp = tq + i0*32;
                float4 k0 = *(const float4*)bp;
                float4 k1 = *(const float4*)(bp + 4);
                float4 f = sf[b];
                float s0 = k0.x*f.x;
                s0 = fmaf(k0.y, f.y, s0);
                s0 = fmaf(k0.z, f.z, s0);
                s0 = fmaf(k0.w, f.w, s0);
                float s1 = k1.x*f.x;
                s1 = fmaf(k1.y, f.y, s1);
                s1 = fmaf(k1.z, f.z, s1);
                s1 = fmaf(k1.w, f.w, s1);
                acc += fmaf(tt, s1 - s0, s0);
            }
        }
    } else {
        #pragma unroll 4
        for (int it = 0; it < NAP/8; it++) {
            int b = p + it*8;
            float2 uv = urow[b];
            int off = __float_as_int(uv.y);
            if (off >= 0) {
                const float* bp = tq + off;
                float4 k0 = *(const float4*)bp;
                float4 k1 = *(const float4*)(bp + 4);
                float4 f = sf[b];
                float s0 = k0.x*f.x;
                s0 = fmaf(k0.y, f.y, s0);
                s0 = fmaf(k0.z, f.z, s0);
                s0 = fmaf(k0.w, f.w, s0);
                float s1 = k1.x*f.x;
                s1 = fmaf(k1.y, f.y, s1);
                s1 = fmaf(k1.z, f.z, s1);
                s1 = fmaf(k1.w, f.w, s1);
                acc += fmaf(uv.x, s1 - s0, s0);
            }
        }
    }

    // reduce over the 8 pair slots (lanes differing in bits 2..4)
    acc += __shfl_down_sync(0xffffffffu, acc, 16);
    acc += __shfl_down_sync(0xffffffffu, acc, 8);
    acc += __shfl_down_sync(0xffffffffu, acc, 4);

    if (CLOUD == 0) {
        cnt += __shfl_down_sync(0xffffffffu, cnt, 16);
        cnt += __shfl_down_sync(0xffffffffu, cnt, 8);
        cnt += __shfl_down_sync(0xffffffffu, cnt, 4);
        float nb = rsqrtf((float)max(cnt, 1));
        if (a < NA && lane == 0) g_nbinv[z*NA + a] = nb;
        if (a < NA && lane < 4)
            g_f1[((size_t)z*NA + a)*4 + lane] = acc * nb;
    } else {
        // fused L2-pool partials: f1 component from sf, f2 from acc*nb
        if (lane < 4) {
            float v1 = ((const float*)(sf + a))[q];
            float v2 = 0.0f;
            if (a < NA) {
                float nb = g_nbinv[z*NA + a];
                v2 = acc * nb;
            }
            spp[warp][q]     = v1 * v1;
            spp[warp][q + 4] = v2 * v2;
        }
        __syncthreads();
        if (threadIdx.x < 8) {
            float s = 0.0f;
            #pragma unroll
            for (int w = 0; w < 8; w++) s += spp[w][threadIdx.x];
            g_part[z][blockIdx.x][threadIdx.x] = s;
        }
    }
}

// ---------------- 3. head: pool-reduce + FC + batchnorm -------------------
// grid 4, 512 threads. Thread layout: f = blk*128 + (tid>>2), zg = tid&3;
// each thread evaluates 4 z (short softplus chains). Batch stats combine the
// 4 zg-partners via shfl_xor(1), shfl_xor(2).
__global__ void __launch_bounds__(512) k_head(const float* __restrict__ fcw,
                                              const float* __restrict__ fcb,
                                              const float* __restrict__ bng,
                                              const float* __restrict__ bnb,
                                              const float* __restrict__ ow) {
    int tid = threadIdx.x, blk = blockIdx.x;
    int lane = tid & 31, warp = tid >> 5;
    __shared__ float pooled[BB][8];
    __shared__ float smw[16][4][4];      // [warp][zg][i]

    if (tid < 128) {                     // 16 z x 8 j
        int z = tid >> 3, j = tid & 7;
        float s = 0.0f;
        #pragma unroll
        for (int c = 0; c < NBLK; c++) s += g_part[z][c][j];
        pooled[z][j] = sqrtf(s);
    }
    __syncthreads();

    int f  = blk*128 + (tid >> 2);
    int zg = tid & 3;                    // my 4 batches: z = zg*4 + i
    float bias = fcb[f];
    float w0 = fcw[0*FF + f], w1 = fcw[1*FF + f];
    float w2 = fcw[2*FF + f], w3 = fcw[3*FF + f];
    float w4 = fcw[4*FF + f], w5 = fcw[5*FF + f];
    float w6 = fcw[6*FF + f], w7 = fcw[7*FF + f];

    float hv[4];
    float msum = 0.0f;
    #pragma unroll
    for (int i = 0; i < 4; i++) {
        int z = zg*4 + i;
        float av = bias;
        av = fmaf(pooled[z][0], w0, av);
        av = fmaf(pooled[z][1], w1, av);
        av = fmaf(pooled[z][2], w2, av);
        av = fmaf(pooled[z][3], w3, av);
        av = fmaf(pooled[z][4], w4, av);
        av = fmaf(pooled[z][5], w5, av);
        av = fmaf(pooled[z][6], w6, av);
        av = fmaf(pooled[z][7], w7, av);
        hv[i] = softplus_fast(av);
        msum += hv[i];
    }
    msum += __shfl_xor_sync(0xffffffffu, msum, 1);
    msum += __shfl_xor_sync(0xffffffffu, msum, 2);
    float m = msum * (1.0f / (float)BB);

    float vsum = 0.0f;
    #pragma unroll
    for (int i = 0; i < 4; i++) { float d = hv[i] - m; vsum += d*d; }
    vsum += __shfl_xor_sync(0xffffffffu, vsum, 1);
    vsum += __shfl_xor_sync(0xffffffffu, vsum, 2);
    float v = vsum * (1.0f / (float)BB);

    float sc = rsqrtf(v + 1e-5f) * bng[f];
    float bo = bnb[f];
    float ww = ow[f];

    float acc[4];
    #pragma unroll
    for (int i = 0; i < 4; i++)
        acc[i] = softplus_fast((hv[i] - m) * sc + bo) * ww;

    // reduce across the 8 features in this warp (lanes differing in bits 2..4)
    #pragma unroll
    for (int i = 0; i < 4; i++) {
        acc[i] += __shfl_down_sync(0xffffffffu, acc[i], 16);
        acc[i] += __shfl_down_sync(0xffffffffu, acc[i], 8);
        acc[i] += __shfl_down_sync(0xffffffffu, acc[i], 4);
    }
    if (lane < 4) {
        #pragma unroll
        for (int i = 0; i < 4; i++) smw[warp][lane][i] = acc[i];
    }
    __syncthreads();
    if (tid < BB) {
        int zg2 = tid >> 2, i2 = tid & 3;
        float t = 0.0f;
        #pragma unroll
        for (int w = 0; w < 16; w++) t += smw[w][zg2][i2];
        g_hpart[blk][tid] = t;
    }
}

// ---------------- 4. final combine + sigmoid ------------------------------
__global__ void __launch_bounds__(32) k_out2(const float* __restrict__ ob,
                                             float* __restrict__ out) {
    int z = threadIdx.x;
    if (z < BB) {
        float t = ob[0] + g_hpart[0][z] + g_hpart[1][z] + g_hpart[2][z] + g_hpart[3][z];
        out[z] = 1.0f / (1.0f + __expf(-t));
    }
}

// ---------------- launch --------------------------------------------------
extern "C" void kernel_launch(void* const* d_in, const int* in_sizes, int n_in,
                              void* d_out, int out_size) {
    const float* xyz   = (const float*)d_in[0];
    const int*   Z     = (const int*)  d_in[1];
    const float* emb   = (const float*)d_in[2];
    BuildArgs ba;
    ba.c[0].w0 = (const float*)d_in[3];  ba.c[0].b0 = (const float*)d_in[4];
    ba.c[0].w1 = (const float*)d_in[5];  ba.c[0].b1 = (const float*)d_in[6];
    ba.c[0].w2 = (const float*)d_in[7];  ba.c[0].b2 = (const float*)d_in[8];
    ba.c[0].w3 = (const float*)d_in[9];  ba.c[0].b3 = (const float*)d_in[10];
    ba.c[1].w0 = (const float*)d_in[11]; ba.c[1].b0 = (const float*)d_in[12];
    ba.c[1].w1 = (const float*)d_in[13]; ba.c[1].b1 = (const float*)d_in[14];
    ba.c[1].w2 = (const float*)d_in[15]; ba.c[1].b2 = (const float*)d_in[16];
    ba.c[1].w3 = (const float*)d_in[17]; ba.c[1].b3 = (const float*)d_in[18];
    const float* fc_w  = (const float*)d_in[19];
    const float* fc_b  = (const float*)d_in[20];
    const float* bn_g  = (const float*)d_in[21];
    const float* bn_b  = (const float*)d_in[22];
    const float* out_w = (const float*)d_in[23];
    const float* out_b = (const float*)d_in[24];
    float* out = (float*)d_out;

    // y planes: 0,1 = table build per cloud; 2 = embedding gather
    k_build<<<dim3(MT / PTS, 3), HID + 10>>>(ba, Z, emb);

    dim3 cg(NBLK, BB);
    k_conv<0><<<cg, 256>>>(xyz);
    k_conv<1><<<cg, 256>>>(xyz);
    k_head<<<4, 512>>>(fc_w, fc_b, bn_g, bn_b, out_w);
    k_out2<<<1, 32>>>(out_b, out);
}